// round 1
// baseline (speedup 1.0000x reference)
#include <cuda_runtime.h>

// Problem constants (fixed by the reference)
static constexpr int BATCH = 2;
static constexpr int SEQ   = 2048;
static constexpr int DMODEL = 2048;
static constexpr int QKV_N = 3072;              // 64*(32 + 2*8)
static constexpr int MROWS = BATCH * SEQ;       // 4096

// Scratch (allocation-free rule: __device__ globals)
__device__ float g_qkv[MROWS * QKV_N];          // (b, l, 3072)
__device__ float g_attn[MROWS * DMODEL];        // (b, l, (g h d))

// ---------------------------------------------------------------------------
// 128x128x8 fp32 SGEMM, 256 threads, 8x8 per thread, double-buffered smem.
// A: MxK row-major, B: KxN row-major, C: MxN row-major. M,N mult of 128, K of 8.
// ---------------------------------------------------------------------------
__global__ __launch_bounds__(256, 2) void sgemm128(const float* __restrict__ A,
                                                   const float* __restrict__ Bm,
                                                   float* __restrict__ C,
                                                   int M, int N, int K) {
    __shared__ float As[2][8][128];   // transposed: As[k][m]
    __shared__ float Bs[2][8][128];   // Bs[k][n]

    const int tid = threadIdx.x;
    const int bn = blockIdx.x, bm = blockIdx.y;
    const int tx = tid % 16, ty = tid / 16;

    const int arow = tid >> 1;            // 0..127
    const int acol = (tid & 1) * 4;       // 0 or 4
    const int brow = tid >> 5;            // 0..7
    const int bcol = (tid & 31) * 4;      // 0..124

    const float* Ap = A + (size_t)(bm * 128 + arow) * K + acol;
    const float* Bp = Bm + (size_t)brow * N + bn * 128 + bcol;

    float4 av = *(const float4*)Ap;
    float4 bv = *(const float4*)Bp;
    As[0][acol + 0][arow] = av.x;
    As[0][acol + 1][arow] = av.y;
    As[0][acol + 2][arow] = av.z;
    As[0][acol + 3][arow] = av.w;
    *(float4*)&Bs[0][brow][bcol] = bv;
    __syncthreads();

    float acc[8][8];
#pragma unroll
    for (int i = 0; i < 8; i++)
#pragma unroll
        for (int j = 0; j < 8; j++) acc[i][j] = 0.f;

    const int nt = K >> 3;
    for (int t = 0; t < nt; ++t) {
        const int cur = t & 1;
        if (t + 1 < nt) {
            av = *(const float4*)(Ap + (t + 1) * 8);
            bv = *(const float4*)(Bp + (size_t)(t + 1) * 8 * N);
        }
#pragma unroll
        for (int k = 0; k < 8; ++k) {
            float4 a0 = *(const float4*)&As[cur][k][ty * 4];
            float4 a1 = *(const float4*)&As[cur][k][64 + ty * 4];
            float4 b0 = *(const float4*)&Bs[cur][k][tx * 4];
            float4 b1 = *(const float4*)&Bs[cur][k][64 + tx * 4];
            float a[8] = {a0.x, a0.y, a0.z, a0.w, a1.x, a1.y, a1.z, a1.w};
            float b[8] = {b0.x, b0.y, b0.z, b0.w, b1.x, b1.y, b1.z, b1.w};
#pragma unroll
            for (int i = 0; i < 8; i++)
#pragma unroll
                for (int j = 0; j < 8; j++) acc[i][j] += a[i] * b[j];
        }
        if (t + 1 < nt) {
            const int nxt = cur ^ 1;
            As[nxt][acol + 0][arow] = av.x;
            As[nxt][acol + 1][arow] = av.y;
            As[nxt][acol + 2][arow] = av.z;
            As[nxt][acol + 3][arow] = av.w;
            *(float4*)&Bs[nxt][brow][bcol] = bv;
        }
        __syncthreads();
    }

#pragma unroll
    for (int i = 0; i < 8; i++) {
        int r = bm * 128 + ((i < 4) ? ty * 4 + i : 64 + ty * 4 + (i - 4));
        float4 c0 = {acc[i][0], acc[i][1], acc[i][2], acc[i][3]};
        float4 c1 = {acc[i][4], acc[i][5], acc[i][6], acc[i][7]};
        *(float4*)&C[(size_t)r * N + bn * 128 + tx * 4] = c0;
        *(float4*)&C[(size_t)r * N + bn * 128 + 64 + tx * 4] = c1;
    }
}

// ---------------------------------------------------------------------------
// Flash attention over the scrambled-reshape views, causal.
// CTA = (l-block of 64, q-head hh, batch). 128 threads (16x8).
// Br=64, Bc=32. Q tile 64x64 (pitch 65), K/V tiles 32x64 (pitch 65).
// P tile aliases the K tile. 33,280 B static smem.
// Each thread owns 4 rows (ty*4+i) and:
//   score cols {tx*4+j},  output d-cols {tx*4+j, 32+tx*4+j}.
// ---------------------------------------------------------------------------
__global__ __launch_bounds__(128) void attn_kernel(const float* __restrict__ qkv,
                                                   float* __restrict__ aout) {
    const int lb = blockIdx.x;   // 0..31
    const int hh = blockIdx.y;   // 0..31  (q head; kv head = hh & 7)
    const int b  = blockIdx.z;   // 0..1
    const int h  = hh & 7;
    const float* qb = qkv + (size_t)b * SEQ * QKV_N;

    __shared__ float Qs[64 * 65];
    __shared__ float Ks[32 * 65];   // doubles as P tile
    __shared__ float Vs[32 * 65];

    const int tid = threadIdx.x;
    const int tx = tid & 7, ty = tid >> 3;

    // Load Q tile: rows l = lb*64 + r, dims d
    for (int e = tid; e < 64 * 64; e += 128) {
        int r = e >> 6, d = e & 63;
        int l = lb * 64 + r;
        Qs[r * 65 + d] = qb[hh * 196608 + l * 64 + (l >> 5) * 1024 + d];
    }

    float mrow[4], lrow[4], acc[4][8];
#pragma unroll
    for (int i = 0; i < 4; i++) {
        mrow[i] = -1e30f;
        lrow[i] = 0.f;
#pragma unroll
        for (int j = 0; j < 8; j++) acc[i][j] = 0.f;
    }
    __syncthreads();

    const int jb_max = 2 * lb + 1;  // cover J <= lb*64+63 in 32-col blocks
    for (int jb = 0; jb <= jb_max; ++jb) {
        // Load K/V tiles (32 j-rows x 64 d)
        for (int e = tid; e < 32 * 64; e += 128) {
            int r = e >> 6, d = e & 63;
            int j = jb * 32 + r;
            size_t base = (size_t)2048 + (size_t)h * 786432 + j * 64 + (j >> 3) * 2560 + d;
            Ks[r * 65 + d] = qb[base];
            Vs[r * 65 + d] = qb[base + 512];
        }
        __syncthreads();

        // S = Q K^T  (64x32 tile; this thread: 4 rows x 4 cols)
        float s[4][4];
#pragma unroll
        for (int i = 0; i < 4; i++)
#pragma unroll
            for (int j = 0; j < 4; j++) s[i][j] = 0.f;
#pragma unroll 8
        for (int d = 0; d < 64; ++d) {
            float a[4], bb[4];
#pragma unroll
            for (int i = 0; i < 4; i++) a[i] = Qs[(ty * 4 + i) * 65 + d];
#pragma unroll
            for (int j = 0; j < 4; j++) bb[j] = Ks[(tx * 4 + j) * 65 + d];
#pragma unroll
            for (int i = 0; i < 4; i++)
#pragma unroll
                for (int j = 0; j < 4; j++) s[i][j] += a[i] * bb[j];
        }

        // Online softmax (rows split across the 8 tx threads; reduce via shfl)
#pragma unroll
        for (int i = 0; i < 4; i++) {
            const int Lr = lb * 64 + ty * 4 + i;
            float mx = -1e30f;
#pragma unroll
            for (int j = 0; j < 4; j++) {
                int J = jb * 32 + tx * 4 + j;
                float v = (J <= Lr) ? s[i][j] * 0.125f : -1e30f;
                s[i][j] = v;
                mx = fmaxf(mx, v);
            }
            mx = fmaxf(mx, __shfl_xor_sync(0xffffffffu, mx, 1));
            mx = fmaxf(mx, __shfl_xor_sync(0xffffffffu, mx, 2));
            mx = fmaxf(mx, __shfl_xor_sync(0xffffffffu, mx, 4));
            float mnew = fmaxf(mrow[i], mx);
            float alpha = __expf(mrow[i] - mnew);
            float psum = 0.f;
#pragma unroll
            for (int j = 0; j < 4; j++) {
                float p = __expf(s[i][j] - mnew);
                s[i][j] = p;
                psum += p;
            }
            psum += __shfl_xor_sync(0xffffffffu, psum, 1);
            psum += __shfl_xor_sync(0xffffffffu, psum, 2);
            psum += __shfl_xor_sync(0xffffffffu, psum, 4);
            lrow[i] = lrow[i] * alpha + psum;
            mrow[i] = mnew;
#pragma unroll
            for (int j = 0; j < 8; j++) acc[i][j] *= alpha;
        }

        __syncthreads();   // all S reads of Ks done -> safe to overwrite as P
#pragma unroll
        for (int i = 0; i < 4; i++)
#pragma unroll
            for (int j = 0; j < 4; j++)
                Ks[(tx * 4 + j) * 65 + (ty * 4 + i)] = s[i][j];  // P^T: [c][r]
        __syncthreads();

        // O += P @ V  (P read transposed: Ps[c][r])
#pragma unroll 4
        for (int c = 0; c < 32; ++c) {
            float p[4], vv[8];
#pragma unroll
            for (int i = 0; i < 4; i++) p[i] = Ks[c * 65 + ty * 4 + i];
#pragma unroll
            for (int j = 0; j < 4; j++) {
                vv[j]     = Vs[c * 65 + tx * 4 + j];
                vv[4 + j] = Vs[c * 65 + 32 + tx * 4 + j];
            }
#pragma unroll
            for (int i = 0; i < 4; i++)
#pragma unroll
                for (int j = 0; j < 8; j++) acc[i][j] += p[i] * vv[j];
        }
        __syncthreads();   // before next K/V overwrite
    }

    // Epilogue: normalize and write at rearranged column hh*64 + d
#pragma unroll
    for (int i = 0; i < 4; i++) {
        const int Lr = lb * 64 + ty * 4 + i;
        const float inv = 1.f / lrow[i];
        float* dst = aout + ((size_t)(b * SEQ + Lr)) * DMODEL + hh * 64;
#pragma unroll
        for (int j = 0; j < 4; j++) {
            dst[tx * 4 + j]      = acc[i][j] * inv;
            dst[32 + tx * 4 + j] = acc[i][4 + j] * inv;
        }
    }
}

// ---------------------------------------------------------------------------
extern "C" void kernel_launch(void* const* d_in, const int* in_sizes, int n_in,
                              void* d_out, int out_size) {
    const float* x    = (const float*)d_in[0];
    // d_in[1] = additive causal mask: semantics implemented directly (causal)
    const float* Wqkv = (const float*)d_in[2];
    const float* Wout = (const float*)d_in[3];
    float* out = (float*)d_out;

    float *qkv, *attn;
    cudaGetSymbolAddress((void**)&qkv, g_qkv);
    cudaGetSymbolAddress((void**)&attn, g_attn);

    // 1) QKV projection: (4096x2048) @ (2048x3072)
    dim3 g1(QKV_N / 128, MROWS / 128);
    sgemm128<<<g1, 256>>>(x, Wqkv, qkv, MROWS, QKV_N, DMODEL);

    // 2) Fused flash attention over scrambled views, writes (b,l,(g h d))
    dim3 g2(SEQ / 64, 32, BATCH);
    attn_kernel<<<g2, 128>>>(qkv, attn);

    // 3) Output projection: (4096x2048) @ (2048x2048)
    dim3 g3(DMODEL / 128, MROWS / 128);
    sgemm128<<<g3, 256>>>(attn, Wout, out, MROWS, DMODEL, DMODEL);
}

// round 5
// speedup vs baseline: 1.6979x; 1.6979x over previous
#include <cuda_runtime.h>
#include <cstdint>

// Problem constants
static constexpr int BATCH = 2;
static constexpr int SEQ   = 2048;
static constexpr int DMODEL = 2048;
static constexpr int QKV_N = 3072;
static constexpr int MROWS = BATCH * SEQ;       // 4096

// Scratch (__device__ globals: allocation-free rule)
__device__ float g_qkv[MROWS * QKV_N];
__device__ float g_attn[MROWS * DMODEL];
__device__ float g_xr[MROWS * DMODEL];          // tf32-rounded x
__device__ float g_wqkvT[QKV_N * DMODEL];       // (N,K)
__device__ float g_woutT[DMODEL * DMODEL];

__device__ __forceinline__ uint32_t smem_u32(const void* p) {
    uint32_t a;
    asm("{ .reg .u64 t; cvta.to.shared.u64 t, %1; cvt.u32.u64 %0, t; }" : "=r"(a) : "l"(p));
    return a;
}
// tf32 round: destination of cvt.rna.tf32.f32 must be a b32 register.
__device__ __forceinline__ float to_tf32(float x) {
    uint32_t u;
    asm("cvt.rna.tf32.f32 %0, %1;" : "=r"(u) : "f"(x));
    return __uint_as_float(u);
}
__device__ __forceinline__ void cp_async16(uint32_t dst, const void* src) {
    asm volatile("cp.async.cg.shared.global [%0], [%1], 16;" :: "r"(dst), "l"(src) : "memory");
}
__device__ __forceinline__ void mma_tf32(float& d0, float& d1, float& d2, float& d3,
                                         uint32_t a0, uint32_t a1, uint32_t a2, uint32_t a3,
                                         uint32_t b0, uint32_t b1) {
    asm volatile(
        "mma.sync.aligned.m16n8k8.row.col.f32.tf32.tf32.f32 "
        "{%0,%1,%2,%3}, {%4,%5,%6,%7}, {%8,%9}, {%0,%1,%2,%3};"
        : "+f"(d0), "+f"(d1), "+f"(d2), "+f"(d3)
        : "r"(a0), "r"(a1), "r"(a2), "r"(a3), "r"(b0), "r"(b1));
}

// ---------------------------------------------------------------------------
// Elementwise tf32 round (vectorized)
// ---------------------------------------------------------------------------
__global__ void round_tf32(const float* __restrict__ in, float* __restrict__ out, int n4) {
    int i = blockIdx.x * blockDim.x + threadIdx.x;
    if (i < n4) {
        float4 v = ((const float4*)in)[i];
        v.x = to_tf32(v.x); v.y = to_tf32(v.y);
        v.z = to_tf32(v.z); v.w = to_tf32(v.w);
        ((float4*)out)[i] = v;
    }
}

// ---------------------------------------------------------------------------
// Weight transpose + round-to-tf32:  out[N,K] = tf32(in[K,N])
// ---------------------------------------------------------------------------
__global__ void transpose_tf32(const float* __restrict__ in, float* __restrict__ out,
                               int R, int C) {  // in: RxC
    __shared__ float t[32][33];
    int bx = blockIdx.x * 32, by = blockIdx.y * 32;
#pragma unroll
    for (int i = 0; i < 32; i += 8)
        t[threadIdx.y + i][threadIdx.x] = in[(size_t)(by + threadIdx.y + i) * C + bx + threadIdx.x];
    __syncthreads();
#pragma unroll
    for (int i = 0; i < 32; i += 8)
        out[(size_t)(bx + threadIdx.y + i) * R + by + threadIdx.x] =
            to_tf32(t[threadIdx.x][threadIdx.y + i]);
}

// ---------------------------------------------------------------------------
// TF32 mma.sync GEMM: C[M,N] = A[M,K] @ Bt[N,K]^T
// CTA: 128x128 tile, 256 threads = 8 warps (2 M x 4 N), warp tile 64x32.
// K-chunk 32, cp.async double buffer. smem rows pitch 36 (conflict-free frags).
// Operands must be pre-rounded to tf32.
// ---------------------------------------------------------------------------
static constexpr int PITCH = 36;
static constexpr int TILE_F = 128 * PITCH;       // floats per A or B tile
static constexpr int BUF_F  = 2 * TILE_F;        // A+B per buffer
static constexpr int GEMM_SMEM = 2 * BUF_F * 4;  // bytes (73728)

__global__ __launch_bounds__(256) void gemm_mma(const float* __restrict__ A,
                                                const float* __restrict__ Bt,
                                                float* __restrict__ C,
                                                int N, int K) {
    extern __shared__ float sm[];
    const int tid = threadIdx.x;
    const int wid = tid >> 5, lane = tid & 31;
    const int g = lane >> 2, tg = lane & 3;      // mma group / thread-in-group
    const int wm = wid & 1, wn = wid >> 1;       // warp grid 2(M) x 4(N)
    const int bn = blockIdx.x, bm = blockIdx.y;

    const float* Ab = A + (size_t)(bm * 128) * K;
    const float* Bb = Bt + (size_t)(bn * 128) * K;
    const uint32_t smb = smem_u32(sm);

    // per-thread cp.async mapping: 4 chunks of 16B for A, 4 for B
    const int crow[4] = {(tid + 0) >> 3, (tid + 256) >> 3, (tid + 512) >> 3, (tid + 768) >> 3};
    const int ccol = (tid & 7) * 4;              // float offset within 32-col chunk

    float acc[4][4][4];
#pragma unroll
    for (int mi = 0; mi < 4; mi++)
#pragma unroll
        for (int ni = 0; ni < 4; ni++)
#pragma unroll
            for (int q = 0; q < 4; q++) acc[mi][ni][q] = 0.f;

    const int NT = K >> 5;

    // prologue: load tile 0 into buffer 0
    {
#pragma unroll
        for (int i = 0; i < 4; i++) {
            int r = crow[i];
            uint32_t sa = smb + (uint32_t)((r * PITCH + ccol) * 4);
            cp_async16(sa, Ab + (size_t)r * K + ccol);
            cp_async16(sa + TILE_F * 4, Bb + (size_t)r * K + ccol);
        }
        asm volatile("cp.async.commit_group;" ::: "memory");
    }

    for (int t = 0; t < NT; ++t) {
        const int buf = t & 1;
        if (t + 1 < NT) {
            const float* Ac = Ab + (t + 1) * 32;
            const float* Bc = Bb + (t + 1) * 32;
            const uint32_t sb = smb + (uint32_t)(((buf ^ 1) * BUF_F) * 4);
#pragma unroll
            for (int i = 0; i < 4; i++) {
                int r = crow[i];
                uint32_t sa = sb + (uint32_t)((r * PITCH + ccol) * 4);
                cp_async16(sa, Ac + (size_t)r * K + ccol);
                cp_async16(sa + TILE_F * 4, Bc + (size_t)r * K + ccol);
            }
            asm volatile("cp.async.commit_group;" ::: "memory");
            asm volatile("cp.async.wait_group 1;" ::: "memory");
        } else {
            asm volatile("cp.async.wait_group 0;" ::: "memory");
        }
        __syncthreads();

        const float* As = sm + buf * BUF_F;
        const float* Bs = As + TILE_F;
#pragma unroll
        for (int kk = 0; kk < 4; ++kk) {
            const int k0 = kk * 8;
            uint32_t bf[4][2];
#pragma unroll
            for (int ni = 0; ni < 4; ni++) {
                const float* bp = Bs + (wn * 32 + ni * 8 + g) * PITCH + k0 + tg;
                bf[ni][0] = __float_as_uint(bp[0]);
                bf[ni][1] = __float_as_uint(bp[4]);
            }
#pragma unroll
            for (int mi = 0; mi < 4; mi++) {
                const float* ap = As + (wm * 64 + mi * 16 + g) * PITCH + k0 + tg;
                uint32_t a0 = __float_as_uint(ap[0]);
                uint32_t a1 = __float_as_uint(ap[8 * PITCH]);
                uint32_t a2 = __float_as_uint(ap[4]);
                uint32_t a3 = __float_as_uint(ap[8 * PITCH + 4]);
#pragma unroll
                for (int ni = 0; ni < 4; ni++)
                    mma_tf32(acc[mi][ni][0], acc[mi][ni][1], acc[mi][ni][2], acc[mi][ni][3],
                             a0, a1, a2, a3, bf[ni][0], bf[ni][1]);
            }
        }
        __syncthreads();
    }

    // epilogue
#pragma unroll
    for (int mi = 0; mi < 4; mi++) {
        const int row = bm * 128 + wm * 64 + mi * 16 + g;
#pragma unroll
        for (int ni = 0; ni < 4; ni++) {
            const int col = bn * 128 + wn * 32 + ni * 8 + 2 * tg;
            float2 v0 = {acc[mi][ni][0], acc[mi][ni][1]};
            float2 v1 = {acc[mi][ni][2], acc[mi][ni][3]};
            *(float2*)&C[(size_t)row * N + col] = v0;
            *(float2*)&C[(size_t)(row + 8) * N + col] = v1;
        }
    }
}

// ---------------------------------------------------------------------------
// Flash attention (fp32 FFMA) — epilogue rounds to tf32 so the output
// projection's A-operand is pre-rounded.
// ---------------------------------------------------------------------------
__global__ __launch_bounds__(128) void attn_kernel(const float* __restrict__ qkv,
                                                   float* __restrict__ aout) {
    const int lb = blockIdx.x;
    const int hh = blockIdx.y;
    const int b  = blockIdx.z;
    const int h  = hh & 7;
    const float* qb = qkv + (size_t)b * SEQ * QKV_N;

    __shared__ float Qs[64 * 65];
    __shared__ float Ks[32 * 65];
    __shared__ float Vs[32 * 65];

    const int tid = threadIdx.x;
    const int tx = tid & 7, ty = tid >> 3;

    for (int e = tid; e < 64 * 64; e += 128) {
        int r = e >> 6, d = e & 63;
        int l = lb * 64 + r;
        Qs[r * 65 + d] = qb[hh * 196608 + l * 64 + (l >> 5) * 1024 + d];
    }

    float mrow[4], lrow[4], acc[4][8];
#pragma unroll
    for (int i = 0; i < 4; i++) {
        mrow[i] = -1e30f; lrow[i] = 0.f;
#pragma unroll
        for (int j = 0; j < 8; j++) acc[i][j] = 0.f;
    }
    __syncthreads();

    const int jb_max = 2 * lb + 1;
    for (int jb = 0; jb <= jb_max; ++jb) {
        for (int e = tid; e < 32 * 64; e += 128) {
            int r = e >> 6, d = e & 63;
            int j = jb * 32 + r;
            size_t base = (size_t)2048 + (size_t)h * 786432 + j * 64 + (j >> 3) * 2560 + d;
            Ks[r * 65 + d] = qb[base];
            Vs[r * 65 + d] = qb[base + 512];
        }
        __syncthreads();

        float s[4][4];
#pragma unroll
        for (int i = 0; i < 4; i++)
#pragma unroll
            for (int j = 0; j < 4; j++) s[i][j] = 0.f;
#pragma unroll 8
        for (int d = 0; d < 64; ++d) {
            float a[4], bb[4];
#pragma unroll
            for (int i = 0; i < 4; i++) a[i] = Qs[(ty * 4 + i) * 65 + d];
#pragma unroll
            for (int j = 0; j < 4; j++) bb[j] = Ks[(tx * 4 + j) * 65 + d];
#pragma unroll
            for (int i = 0; i < 4; i++)
#pragma unroll
                for (int j = 0; j < 4; j++) s[i][j] += a[i] * bb[j];
        }

#pragma unroll
        for (int i = 0; i < 4; i++) {
            const int Lr = lb * 64 + ty * 4 + i;
            float mx = -1e30f;
#pragma unroll
            for (int j = 0; j < 4; j++) {
                int J = jb * 32 + tx * 4 + j;
                float v = (J <= Lr) ? s[i][j] * 0.125f : -1e30f;
                s[i][j] = v;
                mx = fmaxf(mx, v);
            }
            mx = fmaxf(mx, __shfl_xor_sync(0xffffffffu, mx, 1));
            mx = fmaxf(mx, __shfl_xor_sync(0xffffffffu, mx, 2));
            mx = fmaxf(mx, __shfl_xor_sync(0xffffffffu, mx, 4));
            float mnew = fmaxf(mrow[i], mx);
            float alpha = __expf(mrow[i] - mnew);
            float psum = 0.f;
#pragma unroll
            for (int j = 0; j < 4; j++) {
                float p = __expf(s[i][j] - mnew);
                s[i][j] = p; psum += p;
            }
            psum += __shfl_xor_sync(0xffffffffu, psum, 1);
            psum += __shfl_xor_sync(0xffffffffu, psum, 2);
            psum += __shfl_xor_sync(0xffffffffu, psum, 4);
            lrow[i] = lrow[i] * alpha + psum;
            mrow[i] = mnew;
#pragma unroll
            for (int j = 0; j < 8; j++) acc[i][j] *= alpha;
        }

        __syncthreads();
#pragma unroll
        for (int i = 0; i < 4; i++)
#pragma unroll
            for (int j = 0; j < 4; j++)
                Ks[(tx * 4 + j) * 65 + (ty * 4 + i)] = s[i][j];
        __syncthreads();

#pragma unroll 4
        for (int c = 0; c < 32; ++c) {
            float p[4], vv[8];
#pragma unroll
            for (int i = 0; i < 4; i++) p[i] = Ks[c * 65 + ty * 4 + i];
#pragma unroll
            for (int j = 0; j < 4; j++) {
                vv[j]     = Vs[c * 65 + tx * 4 + j];
                vv[4 + j] = Vs[c * 65 + 32 + tx * 4 + j];
            }
#pragma unroll
            for (int i = 0; i < 4; i++)
#pragma unroll
                for (int j = 0; j < 8; j++) acc[i][j] += p[i] * vv[j];
        }
        __syncthreads();
    }

#pragma unroll
    for (int i = 0; i < 4; i++) {
        const int Lr = lb * 64 + ty * 4 + i;
        const float inv = 1.f / lrow[i];
        float* dst = aout + ((size_t)(b * SEQ + Lr)) * DMODEL + hh * 64;
#pragma unroll
        for (int j = 0; j < 4; j++) {
            dst[tx * 4 + j]      = to_tf32(acc[i][j] * inv);
            dst[32 + tx * 4 + j] = to_tf32(acc[i][4 + j] * inv);
        }
    }
}

// ---------------------------------------------------------------------------
extern "C" void kernel_launch(void* const* d_in, const int* in_sizes, int n_in,
                              void* d_out, int out_size) {
    const float* x    = (const float*)d_in[0];
    const float* Wqkv = (const float*)d_in[2];
    const float* Wout = (const float*)d_in[3];
    float* out = (float*)d_out;

    float *qkv, *attn, *xr, *wqkvT, *woutT;
    cudaGetSymbolAddress((void**)&qkv, g_qkv);
    cudaGetSymbolAddress((void**)&attn, g_attn);
    cudaGetSymbolAddress((void**)&xr, g_xr);
    cudaGetSymbolAddress((void**)&wqkvT, g_wqkvT);
    cudaGetSymbolAddress((void**)&woutT, g_woutT);

    cudaFuncSetAttribute(gemm_mma, cudaFuncAttributeMaxDynamicSharedMemorySize, GEMM_SMEM);

    // Pre-round operands to tf32
    round_tf32<<<(MROWS * DMODEL / 4 + 255) / 256, 256>>>(x, xr, MROWS * DMODEL / 4);
    transpose_tf32<<<dim3(QKV_N / 32, DMODEL / 32), dim3(32, 8)>>>(Wqkv, wqkvT, DMODEL, QKV_N);
    transpose_tf32<<<dim3(DMODEL / 32, DMODEL / 32), dim3(32, 8)>>>(Wout, woutT, DMODEL, DMODEL);

    // 1) QKV projection
    gemm_mma<<<dim3(QKV_N / 128, MROWS / 128), 256, GEMM_SMEM>>>(xr, wqkvT, qkv, QKV_N, DMODEL);

    // 2) Fused flash attention
    attn_kernel<<<dim3(SEQ / 64, 32, BATCH), 128>>>(qkv, attn);

    // 3) Output projection
    gemm_mma<<<dim3(DMODEL / 128, MROWS / 128), 256, GEMM_SMEM>>>(attn, woutT, out, DMODEL, DMODEL);
}

// round 6
// speedup vs baseline: 2.7980x; 1.6479x over previous
#include <cuda_runtime.h>
#include <cstdint>

// Problem constants
static constexpr int BATCH = 2;
static constexpr int SEQ   = 2048;
static constexpr int DMODEL = 2048;
static constexpr int QKV_N = 3072;
static constexpr int MROWS = BATCH * SEQ;       // 4096

// Scratch (__device__ globals: allocation-free rule)
__device__ float g_qkv[MROWS * QKV_N];
__device__ float g_attn[MROWS * DMODEL];
__device__ float g_xr[MROWS * DMODEL];          // tf32-rounded x
__device__ float g_wqkvT[QKV_N * DMODEL];       // (N,K)
__device__ float g_woutT[DMODEL * DMODEL];

__device__ __forceinline__ uint32_t smem_u32(const void* p) {
    uint32_t a;
    asm("{ .reg .u64 t; cvta.to.shared.u64 t, %1; cvt.u32.u64 %0, t; }" : "=r"(a) : "l"(p));
    return a;
}
// tf32 round: destination must be a b32 register.
__device__ __forceinline__ float to_tf32(float x) {
    uint32_t u;
    asm("cvt.rna.tf32.f32 %0, %1;" : "=r"(u) : "f"(x));
    return __uint_as_float(u);
}
__device__ __forceinline__ void cp_async16(uint32_t dst, const void* src) {
    asm volatile("cp.async.cg.shared.global [%0], [%1], 16;" :: "r"(dst), "l"(src) : "memory");
}
__device__ __forceinline__ void mma_tf32(float& d0, float& d1, float& d2, float& d3,
                                         uint32_t a0, uint32_t a1, uint32_t a2, uint32_t a3,
                                         uint32_t b0, uint32_t b1) {
    asm volatile(
        "mma.sync.aligned.m16n8k8.row.col.f32.tf32.tf32.f32 "
        "{%0,%1,%2,%3}, {%4,%5,%6,%7}, {%8,%9}, {%0,%1,%2,%3};"
        : "+f"(d0), "+f"(d1), "+f"(d2), "+f"(d3)
        : "r"(a0), "r"(a1), "r"(a2), "r"(a3), "r"(b0), "r"(b1));
}

// ---------------------------------------------------------------------------
// Elementwise tf32 round (vectorized)
// ---------------------------------------------------------------------------
__global__ void round_tf32(const float* __restrict__ in, float* __restrict__ out, int n4) {
    int i = blockIdx.x * blockDim.x + threadIdx.x;
    if (i < n4) {
        float4 v = ((const float4*)in)[i];
        v.x = to_tf32(v.x); v.y = to_tf32(v.y);
        v.z = to_tf32(v.z); v.w = to_tf32(v.w);
        ((float4*)out)[i] = v;
    }
}

// ---------------------------------------------------------------------------
// Weight transpose + round-to-tf32:  out[N,K] = tf32(in[K,N])
// ---------------------------------------------------------------------------
__global__ void transpose_tf32(const float* __restrict__ in, float* __restrict__ out,
                               int R, int C) {  // in: RxC
    __shared__ float t[32][33];
    int bx = blockIdx.x * 32, by = blockIdx.y * 32;
#pragma unroll
    for (int i = 0; i < 32; i += 8)
        t[threadIdx.y + i][threadIdx.x] = in[(size_t)(by + threadIdx.y + i) * C + bx + threadIdx.x];
    __syncthreads();
#pragma unroll
    for (int i = 0; i < 32; i += 8)
        out[(size_t)(bx + threadIdx.y + i) * R + by + threadIdx.x] =
            to_tf32(t[threadIdx.x][threadIdx.y + i]);
}

// ---------------------------------------------------------------------------
// TF32 mma.sync GEMM (unchanged from R5 — validated at tensor=50%)
// ---------------------------------------------------------------------------
static constexpr int PITCH = 36;
static constexpr int TILE_F = 128 * PITCH;
static constexpr int BUF_F  = 2 * TILE_F;
static constexpr int GEMM_SMEM = 2 * BUF_F * 4;

__global__ __launch_bounds__(256) void gemm_mma(const float* __restrict__ A,
                                                const float* __restrict__ Bt,
                                                float* __restrict__ C,
                                                int N, int K) {
    extern __shared__ float sm[];
    const int tid = threadIdx.x;
    const int wid = tid >> 5, lane = tid & 31;
    const int g = lane >> 2, tg = lane & 3;
    const int wm = wid & 1, wn = wid >> 1;
    const int bn = blockIdx.x, bm = blockIdx.y;

    const float* Ab = A + (size_t)(bm * 128) * K;
    const float* Bb = Bt + (size_t)(bn * 128) * K;
    const uint32_t smb = smem_u32(sm);

    const int crow[4] = {(tid + 0) >> 3, (tid + 256) >> 3, (tid + 512) >> 3, (tid + 768) >> 3};
    const int ccol = (tid & 7) * 4;

    float acc[4][4][4];
#pragma unroll
    for (int mi = 0; mi < 4; mi++)
#pragma unroll
        for (int ni = 0; ni < 4; ni++)
#pragma unroll
            for (int q = 0; q < 4; q++) acc[mi][ni][q] = 0.f;

    const int NT = K >> 5;
    {
#pragma unroll
        for (int i = 0; i < 4; i++) {
            int r = crow[i];
            uint32_t sa = smb + (uint32_t)((r * PITCH + ccol) * 4);
            cp_async16(sa, Ab + (size_t)r * K + ccol);
            cp_async16(sa + TILE_F * 4, Bb + (size_t)r * K + ccol);
        }
        asm volatile("cp.async.commit_group;" ::: "memory");
    }

    for (int t = 0; t < NT; ++t) {
        const int buf = t & 1;
        if (t + 1 < NT) {
            const float* Ac = Ab + (t + 1) * 32;
            const float* Bc = Bb + (t + 1) * 32;
            const uint32_t sb = smb + (uint32_t)(((buf ^ 1) * BUF_F) * 4);
#pragma unroll
            for (int i = 0; i < 4; i++) {
                int r = crow[i];
                uint32_t sa = sb + (uint32_t)((r * PITCH + ccol) * 4);
                cp_async16(sa, Ac + (size_t)r * K + ccol);
                cp_async16(sa + TILE_F * 4, Bc + (size_t)r * K + ccol);
            }
            asm volatile("cp.async.commit_group;" ::: "memory");
            asm volatile("cp.async.wait_group 1;" ::: "memory");
        } else {
            asm volatile("cp.async.wait_group 0;" ::: "memory");
        }
        __syncthreads();

        const float* As = sm + buf * BUF_F;
        const float* Bs = As + TILE_F;
#pragma unroll
        for (int kk = 0; kk < 4; ++kk) {
            const int k0 = kk * 8;
            uint32_t bf[4][2];
#pragma unroll
            for (int ni = 0; ni < 4; ni++) {
                const float* bp = Bs + (wn * 32 + ni * 8 + g) * PITCH + k0 + tg;
                bf[ni][0] = __float_as_uint(bp[0]);
                bf[ni][1] = __float_as_uint(bp[4]);
            }
#pragma unroll
            for (int mi = 0; mi < 4; mi++) {
                const float* ap = As + (wm * 64 + mi * 16 + g) * PITCH + k0 + tg;
                uint32_t a0 = __float_as_uint(ap[0]);
                uint32_t a1 = __float_as_uint(ap[8 * PITCH]);
                uint32_t a2 = __float_as_uint(ap[4]);
                uint32_t a3 = __float_as_uint(ap[8 * PITCH + 4]);
#pragma unroll
                for (int ni = 0; ni < 4; ni++)
                    mma_tf32(acc[mi][ni][0], acc[mi][ni][1], acc[mi][ni][2], acc[mi][ni][3],
                             a0, a1, a2, a3, bf[ni][0], bf[ni][1]);
            }
        }
        __syncthreads();
    }

#pragma unroll
    for (int mi = 0; mi < 4; mi++) {
        const int row = bm * 128 + wm * 64 + mi * 16 + g;
#pragma unroll
        for (int ni = 0; ni < 4; ni++) {
            const int col = bn * 128 + wn * 32 + ni * 8 + 2 * tg;
            float2 v0 = {acc[mi][ni][0], acc[mi][ni][1]};
            float2 v1 = {acc[mi][ni][2], acc[mi][ni][3]};
            *(float2*)&C[(size_t)row * N + col] = v0;
            *(float2*)&C[(size_t)(row + 8) * N + col] = v1;
        }
    }
}

// ---------------------------------------------------------------------------
// TF32 tensor-core flash attention, causal, over scrambled-reshape views.
// CTA: 128 Q-rows x 1 head x 1 batch. 256 threads = 8 warps, warp = 16 rows.
// Bc = 64. Fragment softmax (quad shfl); P->A-operand via lane shuffles.
// Smem: Q(128x68) K(64x68) V(64x68) = 69632 B dynamic.
// ---------------------------------------------------------------------------
static constexpr int APITCH = 68;
static constexpr int ATTN_SMEM = (128 + 64 + 64) * APITCH * 4;

__global__ __launch_bounds__(256) void attn_mma(const float* __restrict__ qkv,
                                                float* __restrict__ aout) {
    const int lb = blockIdx.x;   // 0..15 (128 rows each)
    const int hh = blockIdx.y;   // q head
    const int b  = blockIdx.z;
    const int h  = hh & 7;       // kv head
    const float* qb = qkv + (size_t)b * SEQ * QKV_N;

    extern __shared__ float smA[];
    float* Qs = smA;                       // 128 x 68
    float* Ks = Qs + 128 * APITCH;         // 64 x 68
    float* Vs = Ks + 64 * APITCH;          // 64 x 68

    const int tid = threadIdx.x;
    const int wid = tid >> 5, lane = tid & 31;
    const int g = lane >> 2, tg = lane & 3;

    // Load Q tile (tf32-rounded)
    for (int e = tid; e < 128 * 64; e += 256) {
        int r = e >> 6, d = e & 63;
        int l = lb * 128 + r;
        Qs[r * APITCH + d] = to_tf32(qb[hh * 196608 + l * 64 + (l >> 5) * 1024 + d]);
    }

    float m0 = -1e30f, m1 = -1e30f, l0 = 0.f, l1 = 0.f;
    float acc[8][4];
#pragma unroll
    for (int dn = 0; dn < 8; dn++)
#pragma unroll
        for (int q = 0; q < 4; q++) acc[dn][q] = 0.f;

    const int Lr0 = lb * 128 + wid * 16 + g;
    const int Lr1 = Lr0 + 8;
    const uint32_t srcA = g * 4 + (tg >> 1);
    const uint32_t srcB = srcA + 2;
    const bool odd = (tg & 1);

    const int jb_max = 2 * lb + 1;
    for (int jb = 0; jb <= jb_max; ++jb) {
        __syncthreads();   // previous iter's V reads done before overwrite (and Q ready at jb=0)
        for (int e = tid; e < 64 * 64; e += 256) {
            int r = e >> 6, d = e & 63;
            int j = jb * 64 + r;
            size_t base = (size_t)2048 + (size_t)h * 786432 + j * 64 + (j >> 3) * 2560 + d;
            Ks[r * APITCH + d] = to_tf32(qb[base]);
            Vs[r * APITCH + d] = to_tf32(qb[base + 512]);
        }
        __syncthreads();

        // ---- S = Q K^T (warp: 16 x 64) ----
        float s[8][4];
#pragma unroll
        for (int ni = 0; ni < 8; ni++)
#pragma unroll
            for (int q = 0; q < 4; q++) s[ni][q] = 0.f;

        const float* qrow0 = Qs + (wid * 16 + g) * APITCH;
        const float* qrow1 = qrow0 + 8 * APITCH;
#pragma unroll
        for (int k0 = 0; k0 < 64; k0 += 8) {
            uint32_t a0 = __float_as_uint(qrow0[k0 + tg]);
            uint32_t a1 = __float_as_uint(qrow1[k0 + tg]);
            uint32_t a2 = __float_as_uint(qrow0[k0 + tg + 4]);
            uint32_t a3 = __float_as_uint(qrow1[k0 + tg + 4]);
#pragma unroll
            for (int ni = 0; ni < 8; ni++) {
                const float* kp = Ks + (ni * 8 + g) * APITCH + k0 + tg;
                mma_tf32(s[ni][0], s[ni][1], s[ni][2], s[ni][3],
                         a0, a1, a2, a3,
                         __float_as_uint(kp[0]), __float_as_uint(kp[4]));
            }
        }

        // ---- online softmax on fragments ----
        const bool domask = (jb >= 2 * lb);
        float mx0 = -1e30f, mx1 = -1e30f;
#pragma unroll
        for (int ni = 0; ni < 8; ni++) {
            int J = jb * 64 + ni * 8 + 2 * tg;
            float v0 = s[ni][0] * 0.125f, v1 = s[ni][1] * 0.125f;
            float v2 = s[ni][2] * 0.125f, v3 = s[ni][3] * 0.125f;
            if (domask) {
                if (J     > Lr0) v0 = -1e30f;
                if (J + 1 > Lr0) v1 = -1e30f;
                if (J     > Lr1) v2 = -1e30f;
                if (J + 1 > Lr1) v3 = -1e30f;
            }
            s[ni][0] = v0; s[ni][1] = v1; s[ni][2] = v2; s[ni][3] = v3;
            mx0 = fmaxf(mx0, fmaxf(v0, v1));
            mx1 = fmaxf(mx1, fmaxf(v2, v3));
        }
        mx0 = fmaxf(mx0, __shfl_xor_sync(0xffffffffu, mx0, 1));
        mx0 = fmaxf(mx0, __shfl_xor_sync(0xffffffffu, mx0, 2));
        mx1 = fmaxf(mx1, __shfl_xor_sync(0xffffffffu, mx1, 1));
        mx1 = fmaxf(mx1, __shfl_xor_sync(0xffffffffu, mx1, 2));

        float mn0 = fmaxf(m0, mx0), mn1 = fmaxf(m1, mx1);
        float al0 = __expf(m0 - mn0), al1 = __expf(m1 - mn1);
        float ps0 = 0.f, ps1 = 0.f;
#pragma unroll
        for (int ni = 0; ni < 8; ni++) {
            s[ni][0] = __expf(s[ni][0] - mn0);
            s[ni][1] = __expf(s[ni][1] - mn0);
            s[ni][2] = __expf(s[ni][2] - mn1);
            s[ni][3] = __expf(s[ni][3] - mn1);
            ps0 += s[ni][0] + s[ni][1];
            ps1 += s[ni][2] + s[ni][3];
        }
        ps0 += __shfl_xor_sync(0xffffffffu, ps0, 1);
        ps0 += __shfl_xor_sync(0xffffffffu, ps0, 2);
        ps1 += __shfl_xor_sync(0xffffffffu, ps1, 1);
        ps1 += __shfl_xor_sync(0xffffffffu, ps1, 2);
        l0 = l0 * al0 + ps0; l1 = l1 * al1 + ps1;
        m0 = mn0; m1 = mn1;
#pragma unroll
        for (int dn = 0; dn < 8; dn++) {
            acc[dn][0] *= al0; acc[dn][1] *= al0;
            acc[dn][2] *= al1; acc[dn][3] *= al1;
        }

        // ---- O += P @ V ; P C-frag -> A-frag via lane shuffles ----
#pragma unroll
        for (int kb = 0; kb < 8; kb++) {
            float t0 = __shfl_sync(0xffffffffu, s[kb][0], srcA);
            float t1 = __shfl_sync(0xffffffffu, s[kb][1], srcA);
            float t2 = __shfl_sync(0xffffffffu, s[kb][2], srcA);
            float t3 = __shfl_sync(0xffffffffu, s[kb][3], srcA);
            float u0 = __shfl_sync(0xffffffffu, s[kb][0], srcB);
            float u1 = __shfl_sync(0xffffffffu, s[kb][1], srcB);
            float u2 = __shfl_sync(0xffffffffu, s[kb][2], srcB);
            float u3 = __shfl_sync(0xffffffffu, s[kb][3], srcB);
            uint32_t a0 = __float_as_uint(to_tf32(odd ? t1 : t0));  // P[g   ][kb*8+tg]
            uint32_t a1 = __float_as_uint(to_tf32(odd ? t3 : t2));  // P[g+8 ][kb*8+tg]
            uint32_t a2 = __float_as_uint(to_tf32(odd ? u1 : u0));  // P[g   ][kb*8+tg+4]
            uint32_t a3 = __float_as_uint(to_tf32(odd ? u3 : u2));  // P[g+8 ][kb*8+tg+4]
            const float* vk0 = Vs + (kb * 8 + tg) * APITCH;
            const float* vk1 = Vs + (kb * 8 + tg + 4) * APITCH;
#pragma unroll
            for (int dn = 0; dn < 8; dn++) {
                mma_tf32(acc[dn][0], acc[dn][1], acc[dn][2], acc[dn][3],
                         a0, a1, a2, a3,
                         __float_as_uint(vk0[dn * 8 + g]),
                         __float_as_uint(vk1[dn * 8 + g]));
            }
        }
    }

    // Epilogue: normalize, round to tf32 (feeds out-proj A operand), write
    const float inv0 = 1.f / l0, inv1 = 1.f / l1;
    const int row0 = lb * 128 + wid * 16 + g;
    float* d0 = aout + (size_t)(b * SEQ + row0) * DMODEL + hh * 64;
    float* d1 = d0 + 8 * DMODEL;
#pragma unroll
    for (int dn = 0; dn < 8; dn++) {
        const int col = dn * 8 + 2 * tg;
        float2 v0 = {to_tf32(acc[dn][0] * inv0), to_tf32(acc[dn][1] * inv0)};
        float2 v1 = {to_tf32(acc[dn][2] * inv1), to_tf32(acc[dn][3] * inv1)};
        *(float2*)(d0 + col) = v0;
        *(float2*)(d1 + col) = v1;
    }
}

// ---------------------------------------------------------------------------
extern "C" void kernel_launch(void* const* d_in, const int* in_sizes, int n_in,
                              void* d_out, int out_size) {
    const float* x    = (const float*)d_in[0];
    const float* Wqkv = (const float*)d_in[2];
    const float* Wout = (const float*)d_in[3];
    float* out = (float*)d_out;

    float *qkv, *attn, *xr, *wqkvT, *woutT;
    cudaGetSymbolAddress((void**)&qkv, g_qkv);
    cudaGetSymbolAddress((void**)&attn, g_attn);
    cudaGetSymbolAddress((void**)&xr, g_xr);
    cudaGetSymbolAddress((void**)&wqkvT, g_wqkvT);
    cudaGetSymbolAddress((void**)&woutT, g_woutT);

    cudaFuncSetAttribute(gemm_mma, cudaFuncAttributeMaxDynamicSharedMemorySize, GEMM_SMEM);
    cudaFuncSetAttribute(attn_mma, cudaFuncAttributeMaxDynamicSharedMemorySize, ATTN_SMEM);

    // Pre-round operands to tf32
    round_tf32<<<(MROWS * DMODEL / 4 + 255) / 256, 256>>>(x, xr, MROWS * DMODEL / 4);
    transpose_tf32<<<dim3(QKV_N / 32, DMODEL / 32), dim3(32, 8)>>>(Wqkv, wqkvT, DMODEL, QKV_N);
    transpose_tf32<<<dim3(DMODEL / 32, DMODEL / 32), dim3(32, 8)>>>(Wout, woutT, DMODEL, DMODEL);

    // 1) QKV projection
    gemm_mma<<<dim3(QKV_N / 128, MROWS / 128), 256, GEMM_SMEM>>>(xr, wqkvT, qkv, QKV_N, DMODEL);

    // 2) Tensor-core flash attention
    attn_mma<<<dim3(SEQ / 128, 32, BATCH), 256, ATTN_SMEM>>>(qkv, attn);

    // 3) Output projection
    gemm_mma<<<dim3(DMODEL / 128, MROWS / 128), 256, GEMM_SMEM>>>(attn, woutT, out, DMODEL, DMODEL);
}

// round 7
// speedup vs baseline: 2.8437x; 1.0163x over previous
#include <cuda_runtime.h>
#include <cstdint>

// Problem constants
static constexpr int BATCH = 2;
static constexpr int SEQ   = 2048;
static constexpr int DMODEL = 2048;
static constexpr int QKV_N = 3072;
static constexpr int MROWS = BATCH * SEQ;       // 4096

// Scratch (__device__ globals: allocation-free rule)
__device__ float g_qkv[MROWS * QKV_N];
__device__ float g_attn[MROWS * DMODEL];        // k-interleaved layout
__device__ float g_xr[MROWS * DMODEL];          // tf32-rounded, k-interleaved
__device__ float g_wqkvT[QKV_N * DMODEL];       // (N,K), k-interleaved
__device__ float g_woutT[DMODEL * DMODEL];      // (N,K), k-interleaved

__device__ __forceinline__ uint32_t smem_u32(const void* p) {
    uint32_t a;
    asm("{ .reg .u64 t; cvta.to.shared.u64 t, %1; cvt.u32.u64 %0, t; }" : "=r"(a) : "l"(p));
    return a;
}
__device__ __forceinline__ float to_tf32(float x) {
    uint32_t u;
    asm("cvt.rna.tf32.f32 %0, %1;" : "=r"(u) : "f"(x));
    return __uint_as_float(u);
}
__device__ __forceinline__ void cp_async16(uint32_t dst, const void* src) {
    asm volatile("cp.async.cg.shared.global [%0], [%1], 16;" :: "r"(dst), "l"(src) : "memory");
}
__device__ __forceinline__ void mma_tf32(float& d0, float& d1, float& d2, float& d3,
                                         uint32_t a0, uint32_t a1, uint32_t a2, uint32_t a3,
                                         uint32_t b0, uint32_t b1) {
    asm volatile(
        "mma.sync.aligned.m16n8k8.row.col.f32.tf32.tf32.f32 "
        "{%0,%1,%2,%3}, {%4,%5,%6,%7}, {%8,%9}, {%0,%1,%2,%3};"
        : "+f"(d0), "+f"(d1), "+f"(d2), "+f"(d3)
        : "r"(a0), "r"(a1), "r"(a2), "r"(a3), "r"(b0), "r"(b1));
}

// ---------------------------------------------------------------------------
// tf32 round + k-interleave within 8-groups: phys p(k) = 2*(k&3) + (k>>2)
//   phys block order = k0,k4,k1,k5,k2,k6,k3,k7
// ---------------------------------------------------------------------------
__global__ void round_perm_tf32(const float* __restrict__ in, float* __restrict__ out, int n8) {
    int i = blockIdx.x * blockDim.x + threadIdx.x;
    if (i < n8) {
        const float4* p = (const float4*)(in + (size_t)i * 8);
        float4 a = p[0], b = p[1];
        float4 o0 = {to_tf32(a.x), to_tf32(b.x), to_tf32(a.y), to_tf32(b.y)};
        float4 o1 = {to_tf32(a.z), to_tf32(b.z), to_tf32(a.w), to_tf32(b.w)};
        float4* q = (float4*)(out + (size_t)i * 8);
        q[0] = o0; q[1] = o1;
    }
}

// Weight transpose + tf32 round + k-interleave of the output k-dim (columns).
__global__ void transpose_tf32(const float* __restrict__ in, float* __restrict__ out,
                               int R, int C) {  // in: RxC (R = k-dim)
    __shared__ float t[32][33];
    int bx = blockIdx.x * 32, by = blockIdx.y * 32;
    int tx = threadIdx.x;
#pragma unroll
    for (int i = 0; i < 32; i += 8)
        t[threadIdx.y + i][tx] = in[(size_t)(by + threadIdx.y + i) * C + bx + tx];
    __syncthreads();
    const int px = (tx & ~7) | (2 * (tx & 3) + ((tx >> 2) & 1));  // permuted k position
#pragma unroll
    for (int i = 0; i < 32; i += 8)
        out[(size_t)(bx + threadIdx.y + i) * R + by + px] =
            to_tf32(t[tx][threadIdx.y + i]);
}

// ---------------------------------------------------------------------------
// TF32 mma.sync GEMM on k-interleaved operands: C[M,N] = A[M,K] @ Bt[N,K]^T
// CTA 128x64 tile, 256 threads = 8 warps (4M x 2N), warp tile 32x32.
// K-chunk 32, cp.async double buffer, XOR-swizzled pitch-32 smem rows.
// All fragment loads are single conflict-free LDS.64 (thanks to k-interleave).
// ---------------------------------------------------------------------------
static constexpr int AS_F = 128 * 32;            // A tile floats
static constexpr int BS_F = 64 * 32;             // B tile floats
static constexpr int BUF2_F = AS_F + BS_F;       // 6144
static constexpr int GEMM_SMEM = 2 * BUF2_F * 4; // 49152 B

__global__ __launch_bounds__(256, 3) void gemm_mma(const float* __restrict__ A,
                                                   const float* __restrict__ Bt,
                                                   float* __restrict__ C,
                                                   int N, int K) {
    extern __shared__ float sm[];
    const int tid = threadIdx.x;
    const int wid = tid >> 5, lane = tid & 31;
    const int g = lane >> 2, tg = lane & 3;
    const int wm = wid & 3, wn = wid >> 2;       // 4(M) x 2(N)
    const int bn = blockIdx.x, bm = blockIdx.y;

    const float* Ab = A + (size_t)(bm * 128) * K;
    const float* Bb = Bt + (size_t)(bn * 64) * K;
    const uint32_t smb = smem_u32(sm);

    float acc[2][4][4];
#pragma unroll
    for (int mi = 0; mi < 2; mi++)
#pragma unroll
        for (int ni = 0; ni < 4; ni++)
#pragma unroll
            for (int q = 0; q < 4; q++) acc[mi][ni][q] = 0.f;

    const int NT = K >> 5;

    // cp.async mapping: A 1024 16B-chunks (4/thread), B 512 (2/thread)
    // chunk c: row = c>>3, cc = c&7; swizzled dst col4 = (cc*4) ^ ((row&3)<<3)
    auto load_tile = [&](int t, uint32_t sbase) {
        const float* Ac = Ab + t * 32;
        const float* Bc = Bb + t * 32;
#pragma unroll
        for (int i = 0; i < 4; i++) {
            int c = tid + i * 256;
            int row = c >> 3, cc = c & 7;
            uint32_t dcol = (uint32_t)((cc * 4) ^ ((row & 3) << 3));
            cp_async16(sbase + (uint32_t)(row * 32 + dcol) * 4, Ac + (size_t)row * K + cc * 4);
        }
#pragma unroll
        for (int i = 0; i < 2; i++) {
            int c = tid + i * 256;
            int row = c >> 3, cc = c & 7;
            uint32_t dcol = (uint32_t)((cc * 4) ^ ((row & 3) << 3));
            cp_async16(sbase + (uint32_t)(AS_F + row * 32 + dcol) * 4, Bc + (size_t)row * K + cc * 4);
        }
        asm volatile("cp.async.commit_group;" ::: "memory");
    };

    load_tile(0, smb);

    const int xo = (g & 3) << 3;                 // fragment XOR term (same for row & row+8)

    for (int t = 0; t < NT; ++t) {
        const int buf = t & 1;
        if (t + 1 < NT) {
            load_tile(t + 1, smb + (uint32_t)((buf ^ 1) * BUF2_F) * 4);
            asm volatile("cp.async.wait_group 1;" ::: "memory");
        } else {
            asm volatile("cp.async.wait_group 0;" ::: "memory");
        }
        __syncthreads();

        const float* As = sm + buf * BUF2_F;
        const float* Bs = As + AS_F;
#pragma unroll
        for (int kk = 0; kk < 4; ++kk) {
            const int col = ((kk * 8 + 2 * tg) ^ xo);
            float2 bf[4];
#pragma unroll
            for (int ni = 0; ni < 4; ni++)
                bf[ni] = *(const float2*)&Bs[(wn * 32 + ni * 8 + g) * 32 + col];
#pragma unroll
            for (int mi = 0; mi < 2; mi++) {
                const int r0 = wm * 32 + mi * 16 + g;
                float2 alo = *(const float2*)&As[r0 * 32 + col];
                float2 ahi = *(const float2*)&As[(r0 + 8) * 32 + col];
                uint32_t a0 = __float_as_uint(alo.x), a1 = __float_as_uint(ahi.x);
                uint32_t a2 = __float_as_uint(alo.y), a3 = __float_as_uint(ahi.y);
#pragma unroll
                for (int ni = 0; ni < 4; ni++)
                    mma_tf32(acc[mi][ni][0], acc[mi][ni][1], acc[mi][ni][2], acc[mi][ni][3],
                             a0, a1, a2, a3,
                             __float_as_uint(bf[ni].x), __float_as_uint(bf[ni].y));
            }
        }
        __syncthreads();
    }

    // epilogue (C is NOT k-interleaved; N-dim is untouched by the permutation)
#pragma unroll
    for (int mi = 0; mi < 2; mi++) {
        const int row = bm * 128 + wm * 32 + mi * 16 + g;
#pragma unroll
        for (int ni = 0; ni < 4; ni++) {
            const int col = bn * 64 + wn * 32 + ni * 8 + 2 * tg;
            float2 v0 = {acc[mi][ni][0], acc[mi][ni][1]};
            float2 v1 = {acc[mi][ni][2], acc[mi][ni][3]};
            *(float2*)&C[(size_t)row * N + col] = v0;
            *(float2*)&C[(size_t)(row + 8) * N + col] = v1;
        }
    }
}

// ---------------------------------------------------------------------------
// TF32 tensor-core flash attention (validated R6). Epilogue now writes the
// k-interleaved layout expected by the out-projection GEMM.
// ---------------------------------------------------------------------------
static constexpr int APITCH = 68;
static constexpr int ATTN_SMEM = (128 + 64 + 64) * APITCH * 4;

__global__ __launch_bounds__(256) void attn_mma(const float* __restrict__ qkv,
                                                float* __restrict__ aout) {
    const int lb = blockIdx.x;
    const int hh = blockIdx.y;
    const int b  = blockIdx.z;
    const int h  = hh & 7;
    const float* qb = qkv + (size_t)b * SEQ * QKV_N;

    extern __shared__ float smA[];
    float* Qs = smA;
    float* Ks = Qs + 128 * APITCH;
    float* Vs = Ks + 64 * APITCH;

    const int tid = threadIdx.x;
    const int wid = tid >> 5, lane = tid & 31;
    const int g = lane >> 2, tg = lane & 3;

    for (int e = tid; e < 128 * 64; e += 256) {
        int r = e >> 6, d = e & 63;
        int l = lb * 128 + r;
        Qs[r * APITCH + d] = to_tf32(qb[hh * 196608 + l * 64 + (l >> 5) * 1024 + d]);
    }

    float m0 = -1e30f, m1 = -1e30f, l0 = 0.f, l1 = 0.f;
    float acc[8][4];
#pragma unroll
    for (int dn = 0; dn < 8; dn++)
#pragma unroll
        for (int q = 0; q < 4; q++) acc[dn][q] = 0.f;

    const int Lr0 = lb * 128 + wid * 16 + g;
    const int Lr1 = Lr0 + 8;
    const uint32_t srcA = g * 4 + (tg >> 1);
    const uint32_t srcB = srcA + 2;
    const bool odd = (tg & 1);

    const int jb_max = 2 * lb + 1;
    for (int jb = 0; jb <= jb_max; ++jb) {
        __syncthreads();
        for (int e = tid; e < 64 * 64; e += 256) {
            int r = e >> 6, d = e & 63;
            int j = jb * 64 + r;
            size_t base = (size_t)2048 + (size_t)h * 786432 + j * 64 + (j >> 3) * 2560 + d;
            Ks[r * APITCH + d] = to_tf32(qb[base]);
            Vs[r * APITCH + d] = to_tf32(qb[base + 512]);
        }
        __syncthreads();

        float s[8][4];
#pragma unroll
        for (int ni = 0; ni < 8; ni++)
#pragma unroll
            for (int q = 0; q < 4; q++) s[ni][q] = 0.f;

        const float* qrow0 = Qs + (wid * 16 + g) * APITCH;
        const float* qrow1 = qrow0 + 8 * APITCH;
#pragma unroll
        for (int k0 = 0; k0 < 64; k0 += 8) {
            uint32_t a0 = __float_as_uint(qrow0[k0 + tg]);
            uint32_t a1 = __float_as_uint(qrow1[k0 + tg]);
            uint32_t a2 = __float_as_uint(qrow0[k0 + tg + 4]);
            uint32_t a3 = __float_as_uint(qrow1[k0 + tg + 4]);
#pragma unroll
            for (int ni = 0; ni < 8; ni++) {
                const float* kp = Ks + (ni * 8 + g) * APITCH + k0 + tg;
                mma_tf32(s[ni][0], s[ni][1], s[ni][2], s[ni][3],
                         a0, a1, a2, a3,
                         __float_as_uint(kp[0]), __float_as_uint(kp[4]));
            }
        }

        const bool domask = (jb >= 2 * lb);
        float mx0 = -1e30f, mx1 = -1e30f;
#pragma unroll
        for (int ni = 0; ni < 8; ni++) {
            int J = jb * 64 + ni * 8 + 2 * tg;
            float v0 = s[ni][0] * 0.125f, v1 = s[ni][1] * 0.125f;
            float v2 = s[ni][2] * 0.125f, v3 = s[ni][3] * 0.125f;
            if (domask) {
                if (J     > Lr0) v0 = -1e30f;
                if (J + 1 > Lr0) v1 = -1e30f;
                if (J     > Lr1) v2 = -1e30f;
                if (J + 1 > Lr1) v3 = -1e30f;
            }
            s[ni][0] = v0; s[ni][1] = v1; s[ni][2] = v2; s[ni][3] = v3;
            mx0 = fmaxf(mx0, fmaxf(v0, v1));
            mx1 = fmaxf(mx1, fmaxf(v2, v3));
        }
        mx0 = fmaxf(mx0, __shfl_xor_sync(0xffffffffu, mx0, 1));
        mx0 = fmaxf(mx0, __shfl_xor_sync(0xffffffffu, mx0, 2));
        mx1 = fmaxf(mx1, __shfl_xor_sync(0xffffffffu, mx1, 1));
        mx1 = fmaxf(mx1, __shfl_xor_sync(0xffffffffu, mx1, 2));

        float mn0 = fmaxf(m0, mx0), mn1 = fmaxf(m1, mx1);
        float al0 = __expf(m0 - mn0), al1 = __expf(m1 - mn1);
        float ps0 = 0.f, ps1 = 0.f;
#pragma unroll
        for (int ni = 0; ni < 8; ni++) {
            s[ni][0] = __expf(s[ni][0] - mn0);
            s[ni][1] = __expf(s[ni][1] - mn0);
            s[ni][2] = __expf(s[ni][2] - mn1);
            s[ni][3] = __expf(s[ni][3] - mn1);
            ps0 += s[ni][0] + s[ni][1];
            ps1 += s[ni][2] + s[ni][3];
        }
        ps0 += __shfl_xor_sync(0xffffffffu, ps0, 1);
        ps0 += __shfl_xor_sync(0xffffffffu, ps0, 2);
        ps1 += __shfl_xor_sync(0xffffffffu, ps1, 1);
        ps1 += __shfl_xor_sync(0xffffffffu, ps1, 2);
        l0 = l0 * al0 + ps0; l1 = l1 * al1 + ps1;
        m0 = mn0; m1 = mn1;
#pragma unroll
        for (int dn = 0; dn < 8; dn++) {
            acc[dn][0] *= al0; acc[dn][1] *= al0;
            acc[dn][2] *= al1; acc[dn][3] *= al1;
        }

#pragma unroll
        for (int kb = 0; kb < 8; kb++) {
            float t0 = __shfl_sync(0xffffffffu, s[kb][0], srcA);
            float t1 = __shfl_sync(0xffffffffu, s[kb][1], srcA);
            float t2 = __shfl_sync(0xffffffffu, s[kb][2], srcA);
            float t3 = __shfl_sync(0xffffffffu, s[kb][3], srcA);
            float u0 = __shfl_sync(0xffffffffu, s[kb][0], srcB);
            float u1 = __shfl_sync(0xffffffffu, s[kb][1], srcB);
            float u2 = __shfl_sync(0xffffffffu, s[kb][2], srcB);
            float u3 = __shfl_sync(0xffffffffu, s[kb][3], srcB);
            uint32_t a0 = __float_as_uint(to_tf32(odd ? t1 : t0));
            uint32_t a1 = __float_as_uint(to_tf32(odd ? t3 : t2));
            uint32_t a2 = __float_as_uint(to_tf32(odd ? u1 : u0));
            uint32_t a3 = __float_as_uint(to_tf32(odd ? u3 : u2));
            const float* vk0 = Vs + (kb * 8 + tg) * APITCH;
            const float* vk1 = Vs + (kb * 8 + tg + 4) * APITCH;
#pragma unroll
            for (int dn = 0; dn < 8; dn++) {
                mma_tf32(acc[dn][0], acc[dn][1], acc[dn][2], acc[dn][3],
                         a0, a1, a2, a3,
                         __float_as_uint(vk0[dn * 8 + g]),
                         __float_as_uint(vk1[dn * 8 + g]));
            }
        }
    }

    // Epilogue: normalize, tf32-round, write k-INTERLEAVED (p8 within 8-blocks)
    const float inv0 = 1.f / l0, inv1 = 1.f / l1;
    const int row0 = lb * 128 + wid * 16 + g;
    float* d0 = aout + (size_t)(b * SEQ + row0) * DMODEL + hh * 64;
    float* d1 = d0 + 8 * DMODEL;
    const int lc0 = 2 * tg, lc1 = 2 * tg + 1;
    const int pc0 = 2 * (lc0 & 3) + (lc0 >> 2);
    const int pc1 = 2 * (lc1 & 3) + (lc1 >> 2);
#pragma unroll
    for (int dn = 0; dn < 8; dn++) {
        d0[dn * 8 + pc0] = to_tf32(acc[dn][0] * inv0);
        d0[dn * 8 + pc1] = to_tf32(acc[dn][1] * inv0);
        d1[dn * 8 + pc0] = to_tf32(acc[dn][2] * inv1);
        d1[dn * 8 + pc1] = to_tf32(acc[dn][3] * inv1);
    }
}

// ---------------------------------------------------------------------------
extern "C" void kernel_launch(void* const* d_in, const int* in_sizes, int n_in,
                              void* d_out, int out_size) {
    const float* x    = (const float*)d_in[0];
    const float* Wqkv = (const float*)d_in[2];
    const float* Wout = (const float*)d_in[3];
    float* out = (float*)d_out;

    float *qkv, *attn, *xr, *wqkvT, *woutT;
    cudaGetSymbolAddress((void**)&qkv, g_qkv);
    cudaGetSymbolAddress((void**)&attn, g_attn);
    cudaGetSymbolAddress((void**)&xr, g_xr);
    cudaGetSymbolAddress((void**)&wqkvT, g_wqkvT);
    cudaGetSymbolAddress((void**)&woutT, g_woutT);

    cudaFuncSetAttribute(gemm_mma, cudaFuncAttributeMaxDynamicSharedMemorySize, GEMM_SMEM);
    cudaFuncSetAttribute(attn_mma, cudaFuncAttributeMaxDynamicSharedMemorySize, ATTN_SMEM);

    // Pre-round + k-interleave operands
    round_perm_tf32<<<(MROWS * DMODEL / 8 + 255) / 256, 256>>>(x, xr, MROWS * DMODEL / 8);
    transpose_tf32<<<dim3(QKV_N / 32, DMODEL / 32), dim3(32, 8)>>>(Wqkv, wqkvT, DMODEL, QKV_N);
    transpose_tf32<<<dim3(DMODEL / 32, DMODEL / 32), dim3(32, 8)>>>(Wout, woutT, DMODEL, DMODEL);

    // 1) QKV projection
    gemm_mma<<<dim3(QKV_N / 64, MROWS / 128), 256, GEMM_SMEM>>>(xr, wqkvT, qkv, QKV_N, DMODEL);

    // 2) Tensor-core flash attention (epilogue emits k-interleaved layout)
    attn_mma<<<dim3(SEQ / 128, 32, BATCH), 256, ATTN_SMEM>>>(qkv, attn);

    // 3) Output projection
    gemm_mma<<<dim3(DMODEL / 64, MROWS / 128), 256, GEMM_SMEM>>>(attn, woutT, out, DMODEL, DMODEL);
}

// round 9
// speedup vs baseline: 2.8443x; 1.0002x over previous
#include <cuda_runtime.h>
#include <cstdint>

// Problem constants
static constexpr int BATCH = 2;
static constexpr int SEQ   = 2048;
static constexpr int DMODEL = 2048;
static constexpr int QKV_N = 3072;
static constexpr int MROWS = BATCH * SEQ;       // 4096

// Scratch (__device__ globals: allocation-free rule)
__device__ float g_qkv[MROWS * QKV_N];
__device__ float g_attn[MROWS * DMODEL];        // k-interleaved layout
__device__ float g_xr[MROWS * DMODEL];          // tf32-rounded, k-interleaved
__device__ float g_wqkvT[QKV_N * DMODEL];       // (N,K), k-interleaved
__device__ float g_woutT[DMODEL * DMODEL];      // (N,K), k-interleaved

__device__ __forceinline__ uint32_t smem_u32(const void* p) {
    uint32_t a;
    asm("{ .reg .u64 t; cvta.to.shared.u64 t, %1; cvt.u32.u64 %0, t; }" : "=r"(a) : "l"(p));
    return a;
}
__device__ __forceinline__ float to_tf32(float x) {
    uint32_t u;
    asm("cvt.rna.tf32.f32 %0, %1;" : "=r"(u) : "f"(x));
    return __uint_as_float(u);
}
__device__ __forceinline__ void cp_async16(uint32_t dst, const void* src) {
    asm volatile("cp.async.cg.shared.global [%0], [%1], 16;" :: "r"(dst), "l"(src) : "memory");
}
__device__ __forceinline__ void mma_tf32(float& d0, float& d1, float& d2, float& d3,
                                         uint32_t a0, uint32_t a1, uint32_t a2, uint32_t a3,
                                         uint32_t b0, uint32_t b1) {
    asm volatile(
        "mma.sync.aligned.m16n8k8.row.col.f32.tf32.tf32.f32 "
        "{%0,%1,%2,%3}, {%4,%5,%6,%7}, {%8,%9}, {%0,%1,%2,%3};"
        : "+f"(d0), "+f"(d1), "+f"(d2), "+f"(d3)
        : "r"(a0), "r"(a1), "r"(a2), "r"(a3), "r"(b0), "r"(b1));
}

// ---------------------------------------------------------------------------
// tf32 round + k-interleave within 8-groups: phys p(k) = 2*(k&3) + (k>>2)
//   phys block order = k0,k4,k1,k5,k2,k6,k3,k7
// ---------------------------------------------------------------------------
__global__ void round_perm_tf32(const float* __restrict__ in, float* __restrict__ out, int n8) {
    int i = blockIdx.x * blockDim.x + threadIdx.x;
    if (i < n8) {
        const float4* p = (const float4*)(in + (size_t)i * 8);
        float4 a = p[0], b = p[1];
        float4 o0 = {to_tf32(a.x), to_tf32(b.x), to_tf32(a.y), to_tf32(b.y)};
        float4 o1 = {to_tf32(a.z), to_tf32(b.z), to_tf32(a.w), to_tf32(b.w)};
        float4* q = (float4*)(out + (size_t)i * 8);
        q[0] = o0; q[1] = o1;
    }
}

// Weight transpose + tf32 round + k-interleave of the output k-dim (columns).
__global__ void transpose_tf32(const float* __restrict__ in, float* __restrict__ out,
                               int R, int C) {  // in: RxC (R = k-dim)
    __shared__ float t[32][33];
    int bx = blockIdx.x * 32, by = blockIdx.y * 32;
    int tx = threadIdx.x;
#pragma unroll
    for (int i = 0; i < 32; i += 8)
        t[threadIdx.y + i][tx] = in[(size_t)(by + threadIdx.y + i) * C + bx + tx];
    __syncthreads();
    const int px = (tx & ~7) | (2 * (tx & 3) + ((tx >> 2) & 1));  // permuted k position
#pragma unroll
    for (int i = 0; i < 32; i += 8)
        out[(size_t)(bx + threadIdx.y + i) * R + by + px] =
            to_tf32(t[tx][threadIdx.y + i]);
}

// ---------------------------------------------------------------------------
// TF32 mma.sync GEMM on k-interleaved operands: C[M,N] = A[M,K] @ Bt[N,K]^T
// CTA 128x64 tile, 256 threads = 8 warps (4M x 2N), warp tile 32x32.
// K-chunk 32, cp.async double buffer, XOR-swizzled pitch-32 smem rows.
// All fragment loads are single conflict-free LDS.64 (thanks to k-interleave).
// ---------------------------------------------------------------------------
static constexpr int AS_F = 128 * 32;            // A tile floats
static constexpr int BS_F = 64 * 32;             // B tile floats
static constexpr int BUF2_F = AS_F + BS_F;       // 6144
static constexpr int GEMM_SMEM = 2 * BUF2_F * 4; // 49152 B

__global__ __launch_bounds__(256, 3) void gemm_mma(const float* __restrict__ A,
                                                   const float* __restrict__ Bt,
                                                   float* __restrict__ C,
                                                   int N, int K) {
    extern __shared__ float sm[];
    const int tid = threadIdx.x;
    const int wid = tid >> 5, lane = tid & 31;
    const int g = lane >> 2, tg = lane & 3;
    const int wm = wid & 3, wn = wid >> 2;       // 4(M) x 2(N)
    const int bn = blockIdx.x, bm = blockIdx.y;

    const float* Ab = A + (size_t)(bm * 128) * K;
    const float* Bb = Bt + (size_t)(bn * 64) * K;
    const uint32_t smb = smem_u32(sm);

    float acc[2][4][4];
#pragma unroll
    for (int mi = 0; mi < 2; mi++)
#pragma unroll
        for (int ni = 0; ni < 4; ni++)
#pragma unroll
            for (int q = 0; q < 4; q++) acc[mi][ni][q] = 0.f;

    const int NT = K >> 5;

    // cp.async mapping: A 1024 16B-chunks (4/thread), B 512 (2/thread)
    // chunk c: row = c>>3, cc = c&7; swizzled dst col4 = (cc*4) ^ ((row&3)<<3)
    auto load_tile = [&](int t, uint32_t sbase) {
        const float* Ac = Ab + t * 32;
        const float* Bc = Bb + t * 32;
#pragma unroll
        for (int i = 0; i < 4; i++) {
            int c = tid + i * 256;
            int row = c >> 3, cc = c & 7;
            uint32_t dcol = (uint32_t)((cc * 4) ^ ((row & 3) << 3));
            cp_async16(sbase + (uint32_t)(row * 32 + dcol) * 4, Ac + (size_t)row * K + cc * 4);
        }
#pragma unroll
        for (int i = 0; i < 2; i++) {
            int c = tid + i * 256;
            int row = c >> 3, cc = c & 7;
            uint32_t dcol = (uint32_t)((cc * 4) ^ ((row & 3) << 3));
            cp_async16(sbase + (uint32_t)(AS_F + row * 32 + dcol) * 4, Bc + (size_t)row * K + cc * 4);
        }
        asm volatile("cp.async.commit_group;" ::: "memory");
    };

    load_tile(0, smb);

    const int xo = (g & 3) << 3;                 // fragment XOR term (same for row & row+8)

    for (int t = 0; t < NT; ++t) {
        const int buf = t & 1;
        if (t + 1 < NT) {
            load_tile(t + 1, smb + (uint32_t)((buf ^ 1) * BUF2_F) * 4);
            asm volatile("cp.async.wait_group 1;" ::: "memory");
        } else {
            asm volatile("cp.async.wait_group 0;" ::: "memory");
        }
        __syncthreads();

        const float* As = sm + buf * BUF2_F;
        const float* Bs = As + AS_F;
#pragma unroll
        for (int kk = 0; kk < 4; ++kk) {
            const int col = ((kk * 8 + 2 * tg) ^ xo);
            float2 bf[4];
#pragma unroll
            for (int ni = 0; ni < 4; ni++)
                bf[ni] = *(const float2*)&Bs[(wn * 32 + ni * 8 + g) * 32 + col];
#pragma unroll
            for (int mi = 0; mi < 2; mi++) {
                const int r0 = wm * 32 + mi * 16 + g;
                float2 alo = *(const float2*)&As[r0 * 32 + col];
                float2 ahi = *(const float2*)&As[(r0 + 8) * 32 + col];
                uint32_t a0 = __float_as_uint(alo.x), a1 = __float_as_uint(ahi.x);
                uint32_t a2 = __float_as_uint(alo.y), a3 = __float_as_uint(ahi.y);
#pragma unroll
                for (int ni = 0; ni < 4; ni++)
                    mma_tf32(acc[mi][ni][0], acc[mi][ni][1], acc[mi][ni][2], acc[mi][ni][3],
                             a0, a1, a2, a3,
                             __float_as_uint(bf[ni].x), __float_as_uint(bf[ni].y));
            }
        }
        __syncthreads();
    }

    // epilogue (C is NOT k-interleaved; N-dim is untouched by the permutation)
#pragma unroll
    for (int mi = 0; mi < 2; mi++) {
        const int row = bm * 128 + wm * 32 + mi * 16 + g;
#pragma unroll
        for (int ni = 0; ni < 4; ni++) {
            const int col = bn * 64 + wn * 32 + ni * 8 + 2 * tg;
            float2 v0 = {acc[mi][ni][0], acc[mi][ni][1]};
            float2 v1 = {acc[mi][ni][2], acc[mi][ni][3]};
            *(float2*)&C[(size_t)row * N + col] = v0;
            *(float2*)&C[(size_t)(row + 8) * N + col] = v1;
        }
    }
}

// ---------------------------------------------------------------------------
// TF32 tensor-core flash attention (validated R6). Epilogue now writes the
// k-interleaved layout expected by the out-projection GEMM.
// ---------------------------------------------------------------------------
static constexpr int APITCH = 68;
static constexpr int ATTN_SMEM = (128 + 64 + 64) * APITCH * 4;

__global__ __launch_bounds__(256) void attn_mma(const float* __restrict__ qkv,
                                                float* __restrict__ aout) {
    const int lb = blockIdx.x;
    const int hh = blockIdx.y;
    const int b  = blockIdx.z;
    const int h  = hh & 7;
    const float* qb = qkv + (size_t)b * SEQ * QKV_N;

    extern __shared__ float smA[];
    float* Qs = smA;
    float* Ks = Qs + 128 * APITCH;
    float* Vs = Ks + 64 * APITCH;

    const int tid = threadIdx.x;
    const int wid = tid >> 5, lane = tid & 31;
    const int g = lane >> 2, tg = lane & 3;

    for (int e = tid; e < 128 * 64; e += 256) {
        int r = e >> 6, d = e & 63;
        int l = lb * 128 + r;
        Qs[r * APITCH + d] = to_tf32(qb[hh * 196608 + l * 64 + (l >> 5) * 1024 + d]);
    }

    float m0 = -1e30f, m1 = -1e30f, l0 = 0.f, l1 = 0.f;
    float acc[8][4];
#pragma unroll
    for (int dn = 0; dn < 8; dn++)
#pragma unroll
        for (int q = 0; q < 4; q++) acc[dn][q] = 0.f;

    const int Lr0 = lb * 128 + wid * 16 + g;
    const int Lr1 = Lr0 + 8;
    const uint32_t srcA = g * 4 + (tg >> 1);
    const uint32_t srcB = srcA + 2;
    const bool odd = (tg & 1);

    const int jb_max = 2 * lb + 1;
    for (int jb = 0; jb <= jb_max; ++jb) {
        __syncthreads();
        for (int e = tid; e < 64 * 64; e += 256) {
            int r = e >> 6, d = e & 63;
            int j = jb * 64 + r;
            size_t base = (size_t)2048 + (size_t)h * 786432 + j * 64 + (j >> 3) * 2560 + d;
            Ks[r * APITCH + d] = to_tf32(qb[base]);
            Vs[r * APITCH + d] = to_tf32(qb[base + 512]);
        }
        __syncthreads();

        float s[8][4];
#pragma unroll
        for (int ni = 0; ni < 8; ni++)
#pragma unroll
            for (int q = 0; q < 4; q++) s[ni][q] = 0.f;

        const float* qrow0 = Qs + (wid * 16 + g) * APITCH;
        const float* qrow1 = qrow0 + 8 * APITCH;
#pragma unroll
        for (int k0 = 0; k0 < 64; k0 += 8) {
            uint32_t a0 = __float_as_uint(qrow0[k0 + tg]);
            uint32_t a1 = __float_as_uint(qrow1[k0 + tg]);
            uint32_t a2 = __float_as_uint(qrow0[k0 + tg + 4]);
            uint32_t a3 = __float_as_uint(qrow1[k0 + tg + 4]);
#pragma unroll
            for (int ni = 0; ni < 8; ni++) {
                const float* kp = Ks + (ni * 8 + g) * APITCH + k0 + tg;
                mma_tf32(s[ni][0], s[ni][1], s[ni][2], s[ni][3],
                         a0, a1, a2, a3,
                         __float_as_uint(kp[0]), __float_as_uint(kp[4]));
            }
        }

        const bool domask = (jb >= 2 * lb);
        float mx0 = -1e30f, mx1 = -1e30f;
#pragma unroll
        for (int ni = 0; ni < 8; ni++) {
            int J = jb * 64 + ni * 8 + 2 * tg;
            float v0 = s[ni][0] * 0.125f, v1 = s[ni][1] * 0.125f;
            float v2 = s[ni][2] * 0.125f, v3 = s[ni][3] * 0.125f;
            if (domask) {
                if (J     > Lr0) v0 = -1e30f;
                if (J + 1 > Lr0) v1 = -1e30f;
                if (J     > Lr1) v2 = -1e30f;
                if (J + 1 > Lr1) v3 = -1e30f;
            }
            s[ni][0] = v0; s[ni][1] = v1; s[ni][2] = v2; s[ni][3] = v3;
            mx0 = fmaxf(mx0, fmaxf(v0, v1));
            mx1 = fmaxf(mx1, fmaxf(v2, v3));
        }
        mx0 = fmaxf(mx0, __shfl_xor_sync(0xffffffffu, mx0, 1));
        mx0 = fmaxf(mx0, __shfl_xor_sync(0xffffffffu, mx0, 2));
        mx1 = fmaxf(mx1, __shfl_xor_sync(0xffffffffu, mx1, 1));
        mx1 = fmaxf(mx1, __shfl_xor_sync(0xffffffffu, mx1, 2));

        float mn0 = fmaxf(m0, mx0), mn1 = fmaxf(m1, mx1);
        float al0 = __expf(m0 - mn0), al1 = __expf(m1 - mn1);
        float ps0 = 0.f, ps1 = 0.f;
#pragma unroll
        for (int ni = 0; ni < 8; ni++) {
            s[ni][0] = __expf(s[ni][0] - mn0);
            s[ni][1] = __expf(s[ni][1] - mn0);
            s[ni][2] = __expf(s[ni][2] - mn1);
            s[ni][3] = __expf(s[ni][3] - mn1);
            ps0 += s[ni][0] + s[ni][1];
            ps1 += s[ni][2] + s[ni][3];
        }
        ps0 += __shfl_xor_sync(0xffffffffu, ps0, 1);
        ps0 += __shfl_xor_sync(0xffffffffu, ps0, 2);
        ps1 += __shfl_xor_sync(0xffffffffu, ps1, 1);
        ps1 += __shfl_xor_sync(0xffffffffu, ps1, 2);
        l0 = l0 * al0 + ps0; l1 = l1 * al1 + ps1;
        m0 = mn0; m1 = mn1;
#pragma unroll
        for (int dn = 0; dn < 8; dn++) {
            acc[dn][0] *= al0; acc[dn][1] *= al0;
            acc[dn][2] *= al1; acc[dn][3] *= al1;
        }

#pragma unroll
        for (int kb = 0; kb < 8; kb++) {
            float t0 = __shfl_sync(0xffffffffu, s[kb][0], srcA);
            float t1 = __shfl_sync(0xffffffffu, s[kb][1], srcA);
            float t2 = __shfl_sync(0xffffffffu, s[kb][2], srcA);
            float t3 = __shfl_sync(0xffffffffu, s[kb][3], srcA);
            float u0 = __shfl_sync(0xffffffffu, s[kb][0], srcB);
            float u1 = __shfl_sync(0xffffffffu, s[kb][1], srcB);
            float u2 = __shfl_sync(0xffffffffu, s[kb][2], srcB);
            float u3 = __shfl_sync(0xffffffffu, s[kb][3], srcB);
            uint32_t a0 = __float_as_uint(to_tf32(odd ? t1 : t0));
            uint32_t a1 = __float_as_uint(to_tf32(odd ? t3 : t2));
            uint32_t a2 = __float_as_uint(to_tf32(odd ? u1 : u0));
            uint32_t a3 = __float_as_uint(to_tf32(odd ? u3 : u2));
            const float* vk0 = Vs + (kb * 8 + tg) * APITCH;
            const float* vk1 = Vs + (kb * 8 + tg + 4) * APITCH;
#pragma unroll
            for (int dn = 0; dn < 8; dn++) {
                mma_tf32(acc[dn][0], acc[dn][1], acc[dn][2], acc[dn][3],
                         a0, a1, a2, a3,
                         __float_as_uint(vk0[dn * 8 + g]),
                         __float_as_uint(vk1[dn * 8 + g]));
            }
        }
    }

    // Epilogue: normalize, tf32-round, write k-INTERLEAVED (p8 within 8-blocks)
    const float inv0 = 1.f / l0, inv1 = 1.f / l1;
    const int row0 = lb * 128 + wid * 16 + g;
    float* d0 = aout + (size_t)(b * SEQ + row0) * DMODEL + hh * 64;
    float* d1 = d0 + 8 * DMODEL;
    const int lc0 = 2 * tg, lc1 = 2 * tg + 1;
    const int pc0 = 2 * (lc0 & 3) + (lc0 >> 2);
    const int pc1 = 2 * (lc1 & 3) + (lc1 >> 2);
#pragma unroll
    for (int dn = 0; dn < 8; dn++) {
        d0[dn * 8 + pc0] = to_tf32(acc[dn][0] * inv0);
        d0[dn * 8 + pc1] = to_tf32(acc[dn][1] * inv0);
        d1[dn * 8 + pc0] = to_tf32(acc[dn][2] * inv1);
        d1[dn * 8 + pc1] = to_tf32(acc[dn][3] * inv1);
    }
}

// ---------------------------------------------------------------------------
extern "C" void kernel_launch(void* const* d_in, const int* in_sizes, int n_in,
                              void* d_out, int out_size) {
    const float* x    = (const float*)d_in[0];
    const float* Wqkv = (const float*)d_in[2];
    const float* Wout = (const float*)d_in[3];
    float* out = (float*)d_out;

    float *qkv, *attn, *xr, *wqkvT, *woutT;
    cudaGetSymbolAddress((void**)&qkv, g_qkv);
    cudaGetSymbolAddress((void**)&attn, g_attn);
    cudaGetSymbolAddress((void**)&xr, g_xr);
    cudaGetSymbolAddress((void**)&wqkvT, g_wqkvT);
    cudaGetSymbolAddress((void**)&woutT, g_woutT);

    cudaFuncSetAttribute(gemm_mma, cudaFuncAttributeMaxDynamicSharedMemorySize, GEMM_SMEM);
    cudaFuncSetAttribute(attn_mma, cudaFuncAttributeMaxDynamicSharedMemorySize, ATTN_SMEM);

    // Pre-round + k-interleave operands
    round_perm_tf32<<<(MROWS * DMODEL / 8 + 255) / 256, 256>>>(x, xr, MROWS * DMODEL / 8);
    transpose_tf32<<<dim3(QKV_N / 32, DMODEL / 32), dim3(32, 8)>>>(Wqkv, wqkvT, DMODEL, QKV_N);
    transpose_tf32<<<dim3(DMODEL / 32, DMODEL / 32), dim3(32, 8)>>>(Wout, woutT, DMODEL, DMODEL);

    // 1) QKV projection
    gemm_mma<<<dim3(QKV_N / 64, MROWS / 128), 256, GEMM_SMEM>>>(xr, wqkvT, qkv, QKV_N, DMODEL);

    // 2) Tensor-core flash attention (epilogue emits k-interleaved layout)
    attn_mma<<<dim3(SEQ / 128, 32, BATCH), 256, ATTN_SMEM>>>(qkv, attn);

    // 3) Output projection
    gemm_mma<<<dim3(DMODEL / 64, MROWS / 128), 256, GEMM_SMEM>>>(attn, woutT, out, DMODEL, DMODEL);
}